// round 4
// baseline (speedup 1.0000x reference)
#include <cuda_runtime.h>

#define CLS   1000
#define CLS4  250          // CLS / 4
#define NB    65536        // batch
#define TINV  (1.0f/0.3f)
#define WPB   8            // warps per block in main kernel
#define MAIN_BLOCKS (NB / WPB)   // 8192

__device__ float g_soft[CLS * CLS];      // softmax(-S[c]/T) rows, 4 MB
__device__ float g_partial[MAIN_BLOCKS]; // per-block loss partials
__device__ int   g_t64;                  // 1 if targets are int64

// ---------------------------------------------------------------------------
// Detect target dtype: if int64, the high 32-bit word of each value is 0
// (targets are in [0,1000)). Probability of a false positive with int32 data
// is (1/1000)^32 — negligible. Reads only 256 bytes, safe for either layout.
// ---------------------------------------------------------------------------
__global__ void detect_kernel(const int* __restrict__ t)
{
    int is64 = 1;
    #pragma unroll
    for (int i = 0; i < 32; i++)
        if (t[2 * i + 1] != 0) { is64 = 0; break; }
    g_t64 = is64;
}

// ---------------------------------------------------------------------------
// SOFT[c][:] = softmax(-S[c][:] / T). 1000 blocks x 256 threads.
// ---------------------------------------------------------------------------
__global__ void soft_kernel(const float* __restrict__ S)
{
    __shared__ float row[CLS];
    __shared__ float red[8];
    const int c   = blockIdx.x;
    const int tid = threadIdx.x;
    const float* src = S + (size_t)c * CLS;

    float m = -3.4e38f;
    for (int j = tid; j < CLS; j += 256) {
        float v = -src[j] * TINV;
        row[j] = v;
        m = fmaxf(m, v);
    }
    #pragma unroll
    for (int o = 16; o; o >>= 1) m = fmaxf(m, __shfl_xor_sync(~0u, m, o));
    if ((tid & 31) == 0) red[tid >> 5] = m;
    __syncthreads();
    if (tid == 0) {
        float mm = red[0];
        #pragma unroll
        for (int i = 1; i < 8; i++) mm = fmaxf(mm, red[i]);
        red[0] = mm;
    }
    __syncthreads();
    m = red[0];
    __syncthreads();

    float s = 0.f;
    for (int j = tid; j < CLS; j += 256) {
        float e = __expf(row[j] - m);
        row[j] = e;
        s += e;
    }
    #pragma unroll
    for (int o = 16; o; o >>= 1) s += __shfl_xor_sync(~0u, s, o);
    if ((tid & 31) == 0) red[tid >> 5] = s;
    __syncthreads();
    if (tid == 0) {
        float ss = 0.f;
        #pragma unroll
        for (int i = 0; i < 8; i++) ss += red[i];
        red[0] = ss;
    }
    __syncthreads();
    const float inv = 1.0f / red[0];

    for (int j = tid; j < CLS; j += 256)
        g_soft[(size_t)c * CLS + j] = row[j] * inv;
}

// ---------------------------------------------------------------------------
// Main pass: one warp per sample. float4 lane-strided loads (coalesced).
// Logits kept in registers across the max pass so exp pass needs no reload.
// loss_b = m + log(sum exp(x-m)) - dot(soft_row, x)
// ---------------------------------------------------------------------------
__global__ __launch_bounds__(WPB * 32) void main_kernel(
    const float* __restrict__ logits,
    const void*  __restrict__ targets)
{
    __shared__ float part[WPB];
    const int gw   = (blockIdx.x * blockDim.x + threadIdx.x) >> 5;  // sample id
    const int lane = threadIdx.x & 31;
    const int t64  = g_t64;

    long long t;
    if (t64) t = ((const long long*)targets)[gw];
    else     t = ((const int*)targets)[gw];

    const float4* __restrict__ lg = (const float4*)logits + (size_t)gw * CLS4;
    const float4* __restrict__ sf = (const float4*)g_soft + (size_t)t  * CLS4;

    float4 x[8];
    float m = -3.4e38f, dot = 0.f;

    #pragma unroll
    for (int i = 0; i < 7; i++) {
        const int idx = lane + 32 * i;       // <= 223 < 250, always valid
        x[i] = lg[idx];
        float4 s4 = __ldg(&sf[idx]);
        dot += x[i].x * s4.x + x[i].y * s4.y + x[i].z * s4.z + x[i].w * s4.w;
        m = fmaxf(m, fmaxf(fmaxf(x[i].x, x[i].y), fmaxf(x[i].z, x[i].w)));
    }
    if (lane < 26) {                          // tail: idx 224..249
        const int idx = lane + 224;
        x[7] = lg[idx];
        float4 s4 = __ldg(&sf[idx]);
        dot += x[7].x * s4.x + x[7].y * s4.y + x[7].z * s4.z + x[7].w * s4.w;
        m = fmaxf(m, fmaxf(fmaxf(x[7].x, x[7].y), fmaxf(x[7].z, x[7].w)));
    } else {
        x[7] = make_float4(-3.4e38f, -3.4e38f, -3.4e38f, -3.4e38f);
    }

    #pragma unroll
    for (int o = 16; o; o >>= 1) m = fmaxf(m, __shfl_xor_sync(~0u, m, o));

    float s = 0.f;
    #pragma unroll
    for (int i = 0; i < 8; i++) {
        s += __expf(x[i].x - m);
        s += __expf(x[i].y - m);
        s += __expf(x[i].z - m);
        s += __expf(x[i].w - m);
    }
    #pragma unroll
    for (int o = 16; o; o >>= 1) {
        s   += __shfl_xor_sync(~0u, s,   o);
        dot += __shfl_xor_sync(~0u, dot, o);
    }

    if (lane == 0)
        part[threadIdx.x >> 5] = m + __logf(s) - dot;
    __syncthreads();
    if (threadIdx.x == 0) {
        float acc = 0.f;
        #pragma unroll
        for (int i = 0; i < WPB; i++) acc += part[i];
        g_partial[blockIdx.x] = acc;
    }
}

// ---------------------------------------------------------------------------
// Fold 8192 partials -> mean. Deterministic (no atomics anywhere).
// ---------------------------------------------------------------------------
__global__ void reduce_kernel(float* __restrict__ out)
{
    __shared__ float red[8];
    const int tid = threadIdx.x;   // 256
    float s = 0.f;
    for (int i = tid; i < MAIN_BLOCKS; i += 256) s += g_partial[i];
    #pragma unroll
    for (int o = 16; o; o >>= 1) s += __shfl_xor_sync(~0u, s, o);
    if ((tid & 31) == 0) red[tid >> 5] = s;
    __syncthreads();
    if (tid == 0) {
        float tot = 0.f;
        #pragma unroll
        for (int i = 0; i < 8; i++) tot += red[i];
        out[0] = tot * (1.0f / (float)NB);
    }
}

extern "C" void kernel_launch(void* const* d_in, const int* in_sizes, int n_in,
                              void* d_out, int out_size)
{
    const float* logits  = (const float*)d_in[0];
    const void*  targets = d_in[1];
    const float* simmat  = (const float*)d_in[2];
    float* out = (float*)d_out;

    detect_kernel<<<1, 1>>>((const int*)targets);
    soft_kernel<<<CLS, 256>>>(simmat);
    main_kernel<<<MAIN_BLOCKS, WPB * 32>>>(logits, targets);
    reduce_kernel<<<1, 256>>>(out);
}